// round 14
// baseline (speedup 1.0000x reference)
#include <cuda_runtime.h>

// NeRF fused render — TWO RAYS PER WARP (16 lanes per ray), register-dieted.
// Warp-wide work (prologue, scans, scatter, reduction) serves 2 rays in the
// same issue slots; scans are width-16. Lane owns 8 blocked samples.
// Register diet vs r13: zm recomputed at use (not held live), and rgb dot
// runs BEFORE contraction so the 8 weights die before contraction temps are
// born. launch_bounds(256,6) -> 42-reg cap -> ~75% occupancy.
// NOTE (measured): redux.sync is INT-ONLY on sm_103a; L2 prefetch is neutral.

constexpr int T0 = 64;     // coarse intervals
constexpr int TF = 128;    // fine samples
constexpr int OUTW = 4 + 3 * TF;      // 388 floats per ray
constexpr int WPB = 8;                // warps per block
constexpr int RPB = WPB * 2;          // rays per block = 16
constexpr unsigned FULL = 0xffffffffu;

__device__ __forceinline__ float frcp(float x) {
    float r;
    asm("rcp.approx.f32 %0, %1;" : "=f"(r) : "f"(x));
    return r;
}

__device__ __forceinline__ void contract_pt(float zm,
                                            float ox, float oy, float oz,
                                            float dx, float dy, float dz,
                                            float& cx, float& cy, float& cz)
{
    float x = fmaf(dx, zm, ox);
    float y = fmaf(dy, zm, oy);
    float z = fmaf(dz, zm, oz);
    const float ax = fabsf(x), ay = fabsf(y), az = fabsf(z);
    const float mag = fmaxf(ax, fmaxf(ay, az));
    cx = x; cy = y; cz = z;
    if (mag >= 1.0f) {
        const float im = frcp(mag);
        const float sm = (2.0f - im) * im;
        cx = x * im; cy = y * im; cz = z * im;
        if (ax == mag)      cx = x * sm;   // argmax tie-break order x,y,z
        else if (ay == mag) cy = y * sm;
        else                cz = z * sm;
    }
}

__global__ __launch_bounds__(WPB * 32, 6)
void nerf_render_kernel(const float* __restrict__ rays_o,
                        const float* __restrict__ rays_d,
                        const float* __restrict__ aabb,
                        const float* __restrict__ wc,     // [N, 64]
                        const float* __restrict__ sigmas, // [N, 128]
                        const float* __restrict__ rgbs,   // [N, 128, 3]
                        float* __restrict__ out,          // [N, 388]
                        int N)
{
    __shared__ __align__(16) float s_zed[RPB][TF + 8];   // 129 edges per ray

    const int warp = threadIdx.x >> 5;
    const int lane = threadIdx.x & 31;
    const int sub  = lane & 15;          // lane within the ray's 16-lane group
    const int half = lane >> 4;
    const int ray  = blockIdx.x * RPB + 2 * warp + half;
    if (ray >= N) return;

    // ---- ray + aabb (uniform within each 16-lane half) ----
    const float ox = rays_o[3 * ray + 0];
    const float oy = rays_o[3 * ray + 1];
    const float oz = rays_o[3 * ray + 2];
    const float dx = rays_d[3 * ray + 0];
    const float dy = rays_d[3 * ray + 1];
    const float dz = rays_d[3 * ray + 2];

    float nearv, db;
    {
        const float ix = frcp(dx + 1e-15f);
        const float iy = frcp(dy + 1e-15f);
        const float iz = frcp(dz + 1e-15f);
        const float t0x = (aabb[0] - ox) * ix, t1x = (aabb[3] - ox) * ix;
        const float t0y = (aabb[1] - oy) * iy, t1y = (aabb[4] - oy) * iy;
        const float t0z = (aabb[2] - oz) * iz, t1z = (aabb[5] - oz) * iz;

        float nv = fmaxf(fmaxf(fminf(t0x, t1x), fminf(t0y, t1y)), fminf(t0z, t1z));
        float fv = fminf(fminf(fmaxf(t0x, t1x), fmaxf(t0y, t1y)), fmaxf(t0z, t1z));
        if (fv < nv) { nv = 1e9f; fv = 1e9f; }
        nv = fmaxf(nv, 0.05f);
        nearv = nv;
        db = (fv - nv) * (1.0f / 64.0f);
    }

    // ---- CDF: lane owns weights {4s..4s+3} -> intervals 4s..4s+3 local ----
    {
        const float4 wq = __ldcs(reinterpret_cast<const float4*>(
            wc + (size_t)ray * T0 + 4 * sub));
        const float pA = wq.x + 0.01f;
        const float pB = pA + wq.y + 0.01f;
        const float pC = pB + wq.z + 0.01f;
        const float quad = pC + wq.w + 0.01f;

        float incl = quad;
        #pragma unroll
        for (int o = 1; o < 16; o <<= 1) {
            float v = __shfl_up_sync(FULL, incl, o, 16);
            if (sub >= o) incl += v;
        }
        float excl = __shfl_up_sync(FULL, incl, 1, 16);
        if (sub == 0) excl = 0.0f;
        const float inv_tot = frcp(__shfl_sync(FULL, incl, 15, 16));

        const float cs[5] = {
            fminf(excl * inv_tot, 1.0f),
            fminf((excl + pA) * inv_tot, 1.0f),
            fminf((excl + pB) * inv_tot, 1.0f),
            fminf((excl + pC) * inv_tot, 1.0f),
            fminf(incl * inv_tot, 1.0f)
        };

        float* zed = s_zed[2 * warp + half];
        constexpr float inv129 = 1.0f / 129.0f;
        #pragma unroll
        for (int h = 0; h < 4; ++h) {
            const int k = 4 * sub + h;
            const float a = cs[h];
            const float b = cs[h + 1];

            int j0 = (int)ceilf(fmaf(129.0f, a, -0.5f));
            int j1 = (k == 63) ? 129 : (int)ceilf(fmaf(129.0f, b, -0.5f));
            j0 = max(j0, 0);
            j1 = min(j1, 129);

            const float inv_den = frcp(fmaxf(b - a, 1e-12f));
            const float b0 = fmaf(db, (float)k, nearv);
            const float stepz = inv_den * inv129 * db;
            const float zmax = b0 + db;
            float zval = fmaf(fmaf((float)j0 + 0.5f, inv129, -a) * inv_den, db, b0);

            for (int j = j0; j < j1; ++j) {
                zed[j] = fminf(zval, zmax);   // t>=0 at j0 and increasing
                zval += stepz;
            }
        }
    }
    __syncwarp();

    // ---- blocked compositing: lane owns samples 8s..8s+7 ----
    const float* zed = s_zed[2 * warp + half];
    const int s8 = 8 * sub;
    const float4 za = *reinterpret_cast<const float4*>(&zed[s8]);
    const float4 zb = *reinterpret_cast<const float4*>(&zed[s8 + 4]);
    const float e8 = zed[s8 + 8];

    float p1, p2, p3, p4, p5, p6, p7, Tl;
    {
        const float* sgp = sigmas + (size_t)ray * TF + s8;
        const float4 sgA = __ldcs(reinterpret_cast<const float4*>(sgp));
        const float4 sgB = __ldcs(reinterpret_cast<const float4*>(sgp + 4));
        p1 = sgA.x * (za.y - za.x);
        p2 = p1 + sgA.y * (za.z - za.y);
        p3 = p2 + sgA.z * (za.w - za.z);
        p4 = p3 + sgA.w * (zb.x - za.w);
        p5 = p4 + sgB.x * (zb.y - zb.x);
        p6 = p5 + sgB.y * (zb.z - zb.y);
        p7 = p6 + sgB.z * (zb.w - zb.z);
        Tl = p7 + sgB.w * (e8   - zb.w);
    }

    float iS = Tl;
    #pragma unroll
    for (int o = 1; o < 16; o <<= 1) {
        float v = __shfl_up_sync(FULL, iS, o, 16);
        if (sub >= o) iS += v;
    }
    float S0 = __shfl_up_sync(FULL, iS, 1, 16);
    if (sub == 0) S0 = 0.0f;

    const float E0 = __expf(-S0);
    const float E1 = __expf(-(S0 + p1));
    const float E2 = __expf(-(S0 + p2));
    const float E3 = __expf(-(S0 + p3));
    const float E4 = __expf(-(S0 + p4));
    const float E5 = __expf(-(S0 + p5));
    const float E6 = __expf(-(S0 + p6));
    const float E7 = __expf(-(S0 + p7));
    const float E8 = __expf(-(S0 + Tl));

    const float w0 = E0 - E1, w1 = E1 - E2, w2 = E2 - E3, w3 = E3 - E4;
    const float w4 = E4 - E5, w5 = E5 - E6, w6 = E6 - E7, w7 = E7 - E8;

    // dep: zm recomputed inline (no zm registers held live)
    float dep = w0 * (0.5f * (za.x + za.y))
              + w1 * (0.5f * (za.y + za.z))
              + w2 * (0.5f * (za.z + za.w))
              + w3 * (0.5f * (za.w + zb.x))
              + w4 * (0.5f * (zb.x + zb.y))
              + w5 * (0.5f * (zb.y + zb.z))
              + w6 * (0.5f * (zb.z + zb.w))
              + w7 * (0.5f * (zb.w + e8));

    // ---- rgb dot FIRST (consumes w's, then they die) ----
    const size_t base = (size_t)ray * OUTW;
    float img0, img1, img2;
    {
        const float4* rg4 = reinterpret_cast<const float4*>(
            rgbs + (size_t)ray * TF * 3) + 6 * sub;
        {
            const float4 f0 = __ldcs(rg4 + 0);
            const float4 f1 = __ldcs(rg4 + 1);
            const float4 f2 = __ldcs(rg4 + 2);
            img0 = w0 * f0.x + w1 * f0.w + w2 * f1.z + w3 * f2.y;
            img1 = w0 * f0.y + w1 * f1.x + w2 * f1.w + w3 * f2.z;
            img2 = w0 * f0.z + w1 * f1.y + w2 * f2.x + w3 * f2.w;
        }
        {
            const float4 f3 = __ldcs(rg4 + 3);
            const float4 f4 = __ldcs(rg4 + 4);
            const float4 f5 = __ldcs(rg4 + 5);
            img0 += w4 * f3.x + w5 * f3.w + w6 * f4.z + w7 * f5.y;
            img1 += w4 * f3.y + w5 * f4.x + w6 * f4.w + w7 * f5.z;
            img2 += w4 * f3.z + w5 * f4.y + w6 * f5.x + w7 * f5.w;
        }
    }

    // ---- contraction + packed xyz streaming stores (w's dead here) ----
    {
        float4* xo4 = reinterpret_cast<float4*>(out + base + 4) + 6 * sub;
        {
            float a0x,a0y,a0z, a1x,a1y,a1z, a2x,a2y,a2z, a3x,a3y,a3z;
            contract_pt(0.5f * (za.x + za.y), ox,oy,oz, dx,dy,dz, a0x,a0y,a0z);
            contract_pt(0.5f * (za.y + za.z), ox,oy,oz, dx,dy,dz, a1x,a1y,a1z);
            contract_pt(0.5f * (za.z + za.w), ox,oy,oz, dx,dy,dz, a2x,a2y,a2z);
            contract_pt(0.5f * (za.w + zb.x), ox,oy,oz, dx,dy,dz, a3x,a3y,a3z);
            __stcs(xo4 + 0, make_float4(a0x, a0y, a0z, a1x));
            __stcs(xo4 + 1, make_float4(a1y, a1z, a2x, a2y));
            __stcs(xo4 + 2, make_float4(a2z, a3x, a3y, a3z));
        }
        {
            float a4x,a4y,a4z, a5x,a5y,a5z, a6x,a6y,a6z, a7x,a7y,a7z;
            contract_pt(0.5f * (zb.x + zb.y), ox,oy,oz, dx,dy,dz, a4x,a4y,a4z);
            contract_pt(0.5f * (zb.y + zb.z), ox,oy,oz, dx,dy,dz, a5x,a5y,a5z);
            contract_pt(0.5f * (zb.z + zb.w), ox,oy,oz, dx,dy,dz, a6x,a6y,a6z);
            contract_pt(0.5f * (zb.w + e8),   ox,oy,oz, dx,dy,dz, a7x,a7y,a7z);
            __stcs(xo4 + 3, make_float4(a4x, a4y, a4z, a5x));
            __stcs(xo4 + 4, make_float4(a5y, a5z, a6x, a6y));
            __stcs(xo4 + 5, make_float4(a6z, a7x, a7y, a7z));
        }
    }

    // ---- width-16 transposed reduction (serves both rays at once) ----
    #pragma unroll
    for (int o = 8; o >= 4; o >>= 1) {
        img0 += __shfl_down_sync(FULL, img0, o, 16);
        img1 += __shfl_down_sync(FULL, img1, o, 16);
        img2 += __shfl_down_sync(FULL, img2, o, 16);
        dep  += __shfl_down_sync(FULL, dep,  o, 16);
    }
    // partials in subs 0..3; lane (4q + r) fetches quantity q from sub r
    const int src = sub & 3;
    const float a0 = __shfl_sync(FULL, img0, src, 16);
    const float a1 = __shfl_sync(FULL, img1, src, 16);
    const float a2 = __shfl_sync(FULL, img2, src, 16);
    const float a3 = __shfl_sync(FULL, dep,  src, 16);
    const int q = sub >> 2;
    float m = (q == 0) ? a0 : (q == 1) ? a1 : (q == 2) ? a2 : a3;
    m += __shfl_down_sync(FULL, m, 2, 16);
    m += __shfl_down_sync(FULL, m, 1, 16);
    if (src == 0)
        __stcs(out + base + q, m);   // 4 lanes per ray, one 16B segment each
}

extern "C" void kernel_launch(void* const* d_in, const int* in_sizes, int n_in,
                              void* d_out, int out_size)
{
    const float* rays_o = (const float*)d_in[0];
    const float* rays_d = (const float*)d_in[1];
    const float* aabb   = (const float*)d_in[2];
    const float* wc     = (const float*)d_in[3];
    const float* sigmas = (const float*)d_in[4];
    const float* rgbs   = (const float*)d_in[5];
    float* out = (float*)d_out;

    const int N = in_sizes[0] / 3;   // rays_o has N*3 elements
    const int blocks = (N + RPB - 1) / RPB;
    nerf_render_kernel<<<blocks, WPB * 32>>>(
        rays_o, rays_d, aabb, wc, sigmas, rgbs, out, N);
}

// round 15
// speedup vs baseline: 1.1290x; 1.1290x over previous
#include <cuda_runtime.h>

// NeRF fused render: near/far -> coarse bins -> scatter inverse-CDF sampling ->
// contraction -> alpha compositing.
// One warp per ray (PROVEN best structure; 2-ray/warp loses on smem span).
// Blocked sample ownership (lane owns samples 4l..4l+3). Exp-difference
// compositing (one additive warp scan). Pair-owned CDF intervals.
// rcp.approx divisions; streaming cache hints; BRANCHLESS contraction;
// scatter bounds via cvt.rpi with provably-redundant clamps removed.
// NOTE (measured): redux.sync is INT-ONLY on sm_103a; L2 prefetch neutral;
// smem staging shares the l1tex pipe (never stage what you can recompute).

constexpr int T0 = 64;     // coarse intervals
constexpr int TF = 128;    // fine samples
constexpr int OUTW = 4 + 3 * TF;     // 388 floats per ray
constexpr int WPB = 8;               // warps per block
constexpr unsigned FULL = 0xffffffffu;

__device__ __forceinline__ float frcp(float x) {
    float r;
    asm("rcp.approx.f32 %0, %1;" : "=f"(r) : "f"(x));
    return r;
}

// Branchless mip-NeRF-360 contraction (argmax tie-break order x,y,z).
__device__ __forceinline__ void contract_pt(float zm,
                                            float ox, float oy, float oz,
                                            float dx, float dy, float dz,
                                            float& cx, float& cy, float& cz)
{
    const float x = fmaf(dx, zm, ox);
    const float y = fmaf(dy, zm, oy);
    const float z = fmaf(dz, zm, oz);
    const float ax = fabsf(x), ay = fabsf(y), az = fabsf(z);
    const float mag = fmaxf(ax, fmaxf(ay, az));
    const float im = frcp(mag);
    const float sm = (2.0f - im) * im;
    const bool big = mag >= 1.0f;
    const bool px = (ax == mag);
    const bool py = !px && (ay == mag);
    const bool pz = !px && !py;
    const float fx = big ? (px ? sm : im) : 1.0f;
    const float fy = big ? (py ? sm : im) : 1.0f;
    const float fz = big ? (pz ? sm : im) : 1.0f;
    cx = x * fx;
    cy = y * fy;
    cz = z * fz;
}

__global__ __launch_bounds__(WPB * 32, 8)
void nerf_render_kernel(const float* __restrict__ rays_o,
                        const float* __restrict__ rays_d,
                        const float* __restrict__ aabb,
                        const float* __restrict__ wc,     // [N, 64]
                        const float* __restrict__ sigmas, // [N, 128]
                        const float* __restrict__ rgbs,   // [N, 128, 3]
                        float* __restrict__ out,          // [N, 388]
                        int N)
{
    __shared__ __align__(16) float s_zed[WPB][TF + 8];   // 129 fine edges (+pad)

    const int warp = threadIdx.x >> 5;
    const int lane = threadIdx.x & 31;
    const int ray  = blockIdx.x * WPB + warp;
    if (ray >= N) return;

    // ---- ray + aabb ----
    const float ox = rays_o[3 * ray + 0];
    const float oy = rays_o[3 * ray + 1];
    const float oz = rays_o[3 * ray + 2];
    const float dx = rays_d[3 * ray + 0];
    const float dy = rays_d[3 * ray + 1];
    const float dz = rays_d[3 * ray + 2];

    const float ix = frcp(dx + 1e-15f);
    const float iy = frcp(dy + 1e-15f);
    const float iz = frcp(dz + 1e-15f);
    const float t0x = (aabb[0] - ox) * ix, t1x = (aabb[3] - ox) * ix;
    const float t0y = (aabb[1] - oy) * iy, t1y = (aabb[4] - oy) * iy;
    const float t0z = (aabb[2] - oz) * iz, t1z = (aabb[5] - oz) * iz;

    float nearv = fmaxf(fmaxf(fminf(t0x, t1x), fminf(t0y, t1y)), fminf(t0z, t1z));
    float farv  = fminf(fminf(fmaxf(t0x, t1x), fmaxf(t0y, t1y)), fmaxf(t0z, t1z));
    if (farv < nearv) { nearv = 1e9f; farv = 1e9f; }
    nearv = fmaxf(nearv, 0.05f);
    const float db = (farv - nearv) * (1.0f / 64.0f);   // coarse bin width

    // ---- CDF: lane owns weights {2l, 2l+1} -> intervals 2l, 2l+1 local ----
    const float2 wpair = __ldcs(reinterpret_cast<const float2*>(
        wc + (size_t)ray * T0 + 2 * lane));
    const float wa = wpair.x + 0.01f;
    const float pairw = wa + wpair.y + 0.01f;

    float incl = pairw;
    #pragma unroll
    for (int o = 1; o < 32; o <<= 1) {
        float v = __shfl_up_sync(FULL, incl, o);
        if (lane >= o) incl += v;
    }
    float excl = __shfl_up_sync(FULL, incl, 1);
    if (lane == 0) excl = 0.0f;
    const float inv_tot = frcp(__shfl_sync(FULL, incl, 31));

    const float c_base = fminf(excl * inv_tot, 1.0f);          // C[2l]
    const float c_mid  = fminf((excl + wa) * inv_tot, 1.0f);   // C[2l+1]
    const float c_end  = fminf(incl * inv_tot, 1.0f);          // C[2l+2]

    float* zed = s_zed[warp];

    // ---- scatter fine edges: interval k covers u in [C[k], C[k+1]) ----
    // j0 = ru(129*c0 - 0.5) >= 0 since c0 >= 0; j1 <= 129 since c1 <= 1.
    constexpr float inv129 = 1.0f / 129.0f;
    #pragma unroll
    for (int h = 0; h < 2; ++h) {
        const int k = 2 * lane + h;
        const float c0 = (h == 0) ? c_base : c_mid;
        const float c1 = (h == 0) ? c_mid : c_end;

        const int j0 = __float2int_ru(fmaf(129.0f, c0, -0.5f));
        const int j1 = __float2int_ru(fmaf(129.0f, c1, -0.5f));

        const float inv_den = frcp(fmaxf(c1 - c0, 1e-12f));
        const float b0 = fmaf(db, (float)k, nearv);
        const float step_t = inv_den * inv129;
        float t = fmaf((float)j0 + 0.5f, inv129, -c0) * inv_den;

        for (int j = j0; j < j1; ++j) {
            const float tc = fminf(fmaxf(t, 0.0f), 1.0f);
            zed[j] = fmaf(tc, db, b0);
            t += step_t;
        }
    }
    __syncwarp();

    // ---- blocked compositing: lane owns samples 4l..4l+3 ----
    const float4 z4 = *reinterpret_cast<const float4*>(&zed[4 * lane]);
    const float ztop = zed[TF];                         // zed[128], broadcast
    const float znxt = __shfl_down_sync(FULL, z4.x, 1); // next lane's first edge
    const float e4 = (lane == 31) ? ztop : znxt;

    const float4 sg4 = __ldcs(reinterpret_cast<const float4*>(
        sigmas + (size_t)ray * TF + 4 * lane));

    const float p1 = sg4.x * (z4.y - z4.x);
    const float p2 = p1 + sg4.y * (z4.z - z4.y);
    const float p3 = p2 + sg4.z * (z4.w - z4.z);
    const float Tl = p3 + sg4.w * (e4   - z4.w);   // lane-local optical depth

    // single additive warp scan over lane totals
    float iS = Tl;
    #pragma unroll
    for (int o = 1; o < 32; o <<= 1) {
        float v = __shfl_up_sync(FULL, iS, o);
        if (lane >= o) iS += v;
    }
    float S0 = __shfl_up_sync(FULL, iS, 1);
    if (lane == 0) S0 = 0.0f;

    const float E0 = __expf(-S0);
    const float E1 = __expf(-(S0 + p1));
    const float E2 = __expf(-(S0 + p2));
    const float E3 = __expf(-(S0 + p3));
    const float E4 = __expf(-(S0 + Tl));

    const float w0 = E0 - E1;
    const float w1 = E1 - E2;
    const float w2 = E2 - E3;
    const float w3 = E3 - E4;

    const float zm0 = 0.5f * (z4.x + z4.y);
    const float zm1 = 0.5f * (z4.y + z4.z);
    const float zm2 = 0.5f * (z4.z + z4.w);
    const float zm3 = 0.5f * (z4.w + e4);

    float dep = w0 * zm0 + w1 * zm1 + w2 * zm2 + w3 * zm3;

    // ---- rgb: 3x LDG.128 streaming, compile-time channel mapping ----
    const float4* rg4 = reinterpret_cast<const float4*>(
        rgbs + (size_t)ray * TF * 3) + 3 * lane;
    const float4 f0 = __ldcs(rg4 + 0);
    const float4 f1 = __ldcs(rg4 + 1);
    const float4 f2 = __ldcs(rg4 + 2);

    float img0 = w0 * f0.x + w1 * f0.w + w2 * f1.z + w3 * f2.y;
    float img1 = w0 * f0.y + w1 * f1.x + w2 * f1.w + w3 * f2.z;
    float img2 = w0 * f0.z + w1 * f1.y + w2 * f2.x + w3 * f2.w;

    // ---- branchless contraction + packed xyz streaming stores ----
    float c0x, c0y, c0z, c1x, c1y, c1z, c2x, c2y, c2z, c3x, c3y, c3z;
    contract_pt(zm0, ox, oy, oz, dx, dy, dz, c0x, c0y, c0z);
    contract_pt(zm1, ox, oy, oz, dx, dy, dz, c1x, c1y, c1z);
    contract_pt(zm2, ox, oy, oz, dx, dy, dz, c2x, c2y, c2z);
    contract_pt(zm3, ox, oy, oz, dx, dy, dz, c3x, c3y, c3z);

    const size_t base = (size_t)ray * OUTW;
    float4* xo4 = reinterpret_cast<float4*>(out + base + 4) + 3 * lane;
    __stcs(xo4 + 0, make_float4(c0x, c0y, c0z, c1x));
    __stcs(xo4 + 1, make_float4(c1y, c1z, c2x, c2y));
    __stcs(xo4 + 2, make_float4(c2z, c3x, c3y, c3z));

    // ---- transposed warp reduction: 15 SHFL ----
    #pragma unroll
    for (int o = 16; o >= 8; o >>= 1) {
        img0 += __shfl_down_sync(FULL, img0, o);
        img1 += __shfl_down_sync(FULL, img1, o);
        img2 += __shfl_down_sync(FULL, img2, o);
        dep  += __shfl_down_sync(FULL, dep,  o);
    }
    // partials now in lanes 0..7; lane l fetches quantity (l>>3) from lane (l&7)
    const int src = lane & 7;
    const float a0 = __shfl_sync(FULL, img0, src);
    const float a1 = __shfl_sync(FULL, img1, src);
    const float a2 = __shfl_sync(FULL, img2, src);
    const float a3 = __shfl_sync(FULL, dep,  src);
    const int q = lane >> 3;
    float m = (q == 0) ? a0 : (q == 1) ? a1 : (q == 2) ? a2 : a3;
    #pragma unroll
    for (int o = 4; o > 0; o >>= 1)
        m += __shfl_down_sync(FULL, m, o);
    if (src == 0)
        __stcs(out + base + q, m);   // 4 lanes, one 16B segment
}

extern "C" void kernel_launch(void* const* d_in, const int* in_sizes, int n_in,
                              void* d_out, int out_size)
{
    const float* rays_o = (const float*)d_in[0];
    const float* rays_d = (const float*)d_in[1];
    const float* aabb   = (const float*)d_in[2];
    const float* wc     = (const float*)d_in[3];
    const float* sigmas = (const float*)d_in[4];
    const float* rgbs   = (const float*)d_in[5];
    float* out = (float*)d_out;

    const int N = in_sizes[0] / 3;   // rays_o has N*3 elements
    const int blocks = (N + WPB - 1) / WPB;
    nerf_render_kernel<<<blocks, WPB * 32>>>(
        rays_o, rays_d, aabb, wc, sigmas, rgbs, out, N);
}

// round 16
// speedup vs baseline: 1.1298x; 1.0007x over previous
#include <cuda_runtime.h>

// NeRF fused render: near/far -> coarse bins -> scatter inverse-CDF sampling ->
// contraction -> alpha compositing.
// One warp per ray (proven best). Blocked sample ownership (lane owns samples
// 4l..4l+3). Exp-difference compositing (one additive warp scan). Pair-owned
// CDF intervals. rcp.approx; streaming cache hints; branchless contraction.
// THIS ROUND: launch_bounds(256,7) gives a 36-reg budget so the rgb loads can
// be hoisted ABOVE the optical-depth scan — scan latency hides rgb DRAM latency.
// NOTE (measured): redux.sync is INT-ONLY on sm_103a; L2 prefetch neutral;
// smem staging shares the l1tex pipe; 2-ray/warp loses on smem span.

constexpr int T0 = 64;     // coarse intervals
constexpr int TF = 128;    // fine samples
constexpr int OUTW = 4 + 3 * TF;     // 388 floats per ray
constexpr int WPB = 8;               // warps per block
constexpr unsigned FULL = 0xffffffffu;

__device__ __forceinline__ float frcp(float x) {
    float r;
    asm("rcp.approx.f32 %0, %1;" : "=f"(r) : "f"(x));
    return r;
}

// Branchless mip-NeRF-360 contraction (argmax tie-break order x,y,z).
__device__ __forceinline__ void contract_pt(float zm,
                                            float ox, float oy, float oz,
                                            float dx, float dy, float dz,
                                            float& cx, float& cy, float& cz)
{
    const float x = fmaf(dx, zm, ox);
    const float y = fmaf(dy, zm, oy);
    const float z = fmaf(dz, zm, oz);
    const float ax = fabsf(x), ay = fabsf(y), az = fabsf(z);
    const float mag = fmaxf(ax, fmaxf(ay, az));
    const float im = frcp(mag);
    const float sm = (2.0f - im) * im;
    const bool big = mag >= 1.0f;
    const bool px = (ax == mag);
    const bool py = !px && (ay == mag);
    const bool pz = !px && !py;
    const float fx = big ? (px ? sm : im) : 1.0f;
    const float fy = big ? (py ? sm : im) : 1.0f;
    const float fz = big ? (pz ? sm : im) : 1.0f;
    cx = x * fx;
    cy = y * fy;
    cz = z * fz;
}

__global__ __launch_bounds__(WPB * 32, 7)
void nerf_render_kernel(const float* __restrict__ rays_o,
                        const float* __restrict__ rays_d,
                        const float* __restrict__ aabb,
                        const float* __restrict__ wc,     // [N, 64]
                        const float* __restrict__ sigmas, // [N, 128]
                        const float* __restrict__ rgbs,   // [N, 128, 3]
                        float* __restrict__ out,          // [N, 388]
                        int N)
{
    __shared__ __align__(16) float s_zed[WPB][TF + 8];   // 129 fine edges (+pad)

    const int warp = threadIdx.x >> 5;
    const int lane = threadIdx.x & 31;
    const int ray  = blockIdx.x * WPB + warp;
    if (ray >= N) return;

    // ---- ray + aabb ----
    const float ox = rays_o[3 * ray + 0];
    const float oy = rays_o[3 * ray + 1];
    const float oz = rays_o[3 * ray + 2];
    const float dx = rays_d[3 * ray + 0];
    const float dy = rays_d[3 * ray + 1];
    const float dz = rays_d[3 * ray + 2];

    const float ix = frcp(dx + 1e-15f);
    const float iy = frcp(dy + 1e-15f);
    const float iz = frcp(dz + 1e-15f);
    const float t0x = (aabb[0] - ox) * ix, t1x = (aabb[3] - ox) * ix;
    const float t0y = (aabb[1] - oy) * iy, t1y = (aabb[4] - oy) * iy;
    const float t0z = (aabb[2] - oz) * iz, t1z = (aabb[5] - oz) * iz;

    float nearv = fmaxf(fmaxf(fminf(t0x, t1x), fminf(t0y, t1y)), fminf(t0z, t1z));
    float farv  = fminf(fminf(fmaxf(t0x, t1x), fmaxf(t0y, t1y)), fmaxf(t0z, t1z));
    if (farv < nearv) { nearv = 1e9f; farv = 1e9f; }
    nearv = fmaxf(nearv, 0.05f);
    const float db = (farv - nearv) * (1.0f / 64.0f);   // coarse bin width

    // ---- CDF: lane owns weights {2l, 2l+1} -> intervals 2l, 2l+1 local ----
    const float2 wpair = __ldcs(reinterpret_cast<const float2*>(
        wc + (size_t)ray * T0 + 2 * lane));
    const float wa = wpair.x + 0.01f;
    const float pairw = wa + wpair.y + 0.01f;

    float incl = pairw;
    #pragma unroll
    for (int o = 1; o < 32; o <<= 1) {
        float v = __shfl_up_sync(FULL, incl, o);
        if (lane >= o) incl += v;
    }
    float excl = __shfl_up_sync(FULL, incl, 1);
    if (lane == 0) excl = 0.0f;
    const float inv_tot = frcp(__shfl_sync(FULL, incl, 31));

    const float c_base = fminf(excl * inv_tot, 1.0f);          // C[2l]
    const float c_mid  = fminf((excl + wa) * inv_tot, 1.0f);   // C[2l+1]
    const float c_end  = fminf(incl * inv_tot, 1.0f);          // C[2l+2]

    float* zed = s_zed[warp];

    // ---- scatter fine edges: interval k covers u in [C[k], C[k+1]) ----
    constexpr float inv129 = 1.0f / 129.0f;
    #pragma unroll
    for (int h = 0; h < 2; ++h) {
        const int k = 2 * lane + h;
        const float c0 = (h == 0) ? c_base : c_mid;
        const float c1 = (h == 0) ? c_mid : c_end;

        const int j0 = __float2int_ru(fmaf(129.0f, c0, -0.5f));
        const int j1 = __float2int_ru(fmaf(129.0f, c1, -0.5f));

        const float inv_den = frcp(fmaxf(c1 - c0, 1e-12f));
        const float b0 = fmaf(db, (float)k, nearv);
        const float step_t = inv_den * inv129;
        float t = fmaf((float)j0 + 0.5f, inv129, -c0) * inv_den;

        for (int j = j0; j < j1; ++j) {
            const float tc = fminf(fmaxf(t, 0.0f), 1.0f);
            zed[j] = fmaf(tc, db, b0);
            t += step_t;
        }
    }
    __syncwarp();

    // ---- blocked compositing: lane owns samples 4l..4l+3 ----
    const float4 z4 = *reinterpret_cast<const float4*>(&zed[4 * lane]);
    const float ztop = zed[TF];                         // zed[128], broadcast
    const float znxt = __shfl_down_sync(FULL, z4.x, 1); // next lane's first edge
    const float e4 = (lane == 31) ? ztop : znxt;

    const float4 sg4 = __ldcs(reinterpret_cast<const float4*>(
        sigmas + (size_t)ray * TF + 4 * lane));

    // ---- HOISTED rgb loads: issue before the dependent scan so the scan's
    //      ~200-cycle chain hides their DRAM latency ----
    const float4* rg4 = reinterpret_cast<const float4*>(
        rgbs + (size_t)ray * TF * 3) + 3 * lane;
    const float4 f0 = __ldcs(rg4 + 0);
    const float4 f1 = __ldcs(rg4 + 1);
    const float4 f2 = __ldcs(rg4 + 2);

    const float p1 = sg4.x * (z4.y - z4.x);
    const float p2 = p1 + sg4.y * (z4.z - z4.y);
    const float p3 = p2 + sg4.z * (z4.w - z4.z);
    const float Tl = p3 + sg4.w * (e4   - z4.w);   // lane-local optical depth

    // single additive warp scan over lane totals
    float iS = Tl;
    #pragma unroll
    for (int o = 1; o < 32; o <<= 1) {
        float v = __shfl_up_sync(FULL, iS, o);
        if (lane >= o) iS += v;
    }
    float S0 = __shfl_up_sync(FULL, iS, 1);
    if (lane == 0) S0 = 0.0f;

    const float E0 = __expf(-S0);
    const float E1 = __expf(-(S0 + p1));
    const float E2 = __expf(-(S0 + p2));
    const float E3 = __expf(-(S0 + p3));
    const float E4 = __expf(-(S0 + Tl));

    const float w0 = E0 - E1;
    const float w1 = E1 - E2;
    const float w2 = E2 - E3;
    const float w3 = E3 - E4;

    const float zm0 = 0.5f * (z4.x + z4.y);
    const float zm1 = 0.5f * (z4.y + z4.z);
    const float zm2 = 0.5f * (z4.z + z4.w);
    const float zm3 = 0.5f * (z4.w + e4);

    float dep = w0 * zm0 + w1 * zm1 + w2 * zm2 + w3 * zm3;

    // ---- rgb dot (loads already in flight / landed) ----
    float img0 = w0 * f0.x + w1 * f0.w + w2 * f1.z + w3 * f2.y;
    float img1 = w0 * f0.y + w1 * f1.x + w2 * f1.w + w3 * f2.z;
    float img2 = w0 * f0.z + w1 * f1.y + w2 * f2.x + w3 * f2.w;

    // ---- branchless contraction + packed xyz streaming stores ----
    float c0x, c0y, c0z, c1x, c1y, c1z, c2x, c2y, c2z, c3x, c3y, c3z;
    contract_pt(zm0, ox, oy, oz, dx, dy, dz, c0x, c0y, c0z);
    contract_pt(zm1, ox, oy, oz, dx, dy, dz, c1x, c1y, c1z);
    contract_pt(zm2, ox, oy, oz, dx, dy, dz, c2x, c2y, c2z);
    contract_pt(zm3, ox, oy, oz, dx, dy, dz, c3x, c3y, c3z);

    const size_t base = (size_t)ray * OUTW;
    float4* xo4 = reinterpret_cast<float4*>(out + base + 4) + 3 * lane;
    __stcs(xo4 + 0, make_float4(c0x, c0y, c0z, c1x));
    __stcs(xo4 + 1, make_float4(c1y, c1z, c2x, c2y));
    __stcs(xo4 + 2, make_float4(c2z, c3x, c3y, c3z));

    // ---- transposed warp reduction: 15 SHFL ----
    #pragma unroll
    for (int o = 16; o >= 8; o >>= 1) {
        img0 += __shfl_down_sync(FULL, img0, o);
        img1 += __shfl_down_sync(FULL, img1, o);
        img2 += __shfl_down_sync(FULL, img2, o);
        dep  += __shfl_down_sync(FULL, dep,  o);
    }
    // partials now in lanes 0..7; lane l fetches quantity (l>>3) from lane (l&7)
    const int src = lane & 7;
    const float a0 = __shfl_sync(FULL, img0, src);
    const float a1 = __shfl_sync(FULL, img1, src);
    const float a2 = __shfl_sync(FULL, img2, src);
    const float a3 = __shfl_sync(FULL, dep,  src);
    const int q = lane >> 3;
    float m = (q == 0) ? a0 : (q == 1) ? a1 : (q == 2) ? a2 : a3;
    #pragma unroll
    for (int o = 4; o > 0; o >>= 1)
        m += __shfl_down_sync(FULL, m, o);
    if (src == 0)
        __stcs(out + base + q, m);   // 4 lanes, one 16B segment
}

extern "C" void kernel_launch(void* const* d_in, const int* in_sizes, int n_in,
                              void* d_out, int out_size)
{
    const float* rays_o = (const float*)d_in[0];
    const float* rays_d = (const float*)d_in[1];
    const float* aabb   = (const float*)d_in[2];
    const float* wc     = (const float*)d_in[3];
    const float* sigmas = (const float*)d_in[4];
    const float* rgbs   = (const float*)d_in[5];
    float* out = (float*)d_out;

    const int N = in_sizes[0] / 3;   // rays_o has N*3 elements
    const int blocks = (N + WPB - 1) / WPB;
    nerf_render_kernel<<<blocks, WPB * 32>>>(
        rays_o, rays_d, aabb, wc, sigmas, rgbs, out, N);
}

// round 17
// speedup vs baseline: 1.1798x; 1.0442x over previous
#include <cuda_runtime.h>

// NeRF fused render: near/far -> coarse bins -> scatter inverse-CDF sampling ->
// contraction -> alpha compositing.
// One warp per ray (proven best). Blocked sample ownership (lane owns samples
// 4l..4l+3). Exp-difference compositing (one additive warp scan). Pair-owned
// CDF intervals. rcp.approx; streaming cache hints; branchless contraction.
// THIS ROUND: scatter clamps via .SAT modifier (FMA pipe) instead of FMNMX
// (ALU pipe); dead CDF clamps deleted.
// NOTE (measured): redux.sync is INT-ONLY on sm_103a; L2 prefetch neutral;
// smem staging shares the l1tex pipe; 2-ray/warp loses on smem span;
// occupancy beyond ~85% buys nothing (issue-bound).

constexpr int T0 = 64;     // coarse intervals
constexpr int TF = 128;    // fine samples
constexpr int OUTW = 4 + 3 * TF;     // 388 floats per ray
constexpr int WPB = 8;               // warps per block
constexpr unsigned FULL = 0xffffffffu;

__device__ __forceinline__ float frcp(float x) {
    float r;
    asm("rcp.approx.f32 %0, %1;" : "=f"(r) : "f"(x));
    return r;
}

// Branchless mip-NeRF-360 contraction (argmax tie-break order x,y,z).
__device__ __forceinline__ void contract_pt(float zm,
                                            float ox, float oy, float oz,
                                            float dx, float dy, float dz,
                                            float& cx, float& cy, float& cz)
{
    const float x = fmaf(dx, zm, ox);
    const float y = fmaf(dy, zm, oy);
    const float z = fmaf(dz, zm, oz);
    const float ax = fabsf(x), ay = fabsf(y), az = fabsf(z);
    const float mag = fmaxf(ax, fmaxf(ay, az));
    const float im = frcp(mag);
    const float sm = (2.0f - im) * im;
    const bool big = mag >= 1.0f;
    const bool px = (ax == mag);
    const bool py = !px && (ay == mag);
    const bool pz = !px && !py;
    const float fx = big ? (px ? sm : im) : 1.0f;
    const float fy = big ? (py ? sm : im) : 1.0f;
    const float fz = big ? (pz ? sm : im) : 1.0f;
    cx = x * fx;
    cy = y * fy;
    cz = z * fz;
}

__global__ __launch_bounds__(WPB * 32, 8)
void nerf_render_kernel(const float* __restrict__ rays_o,
                        const float* __restrict__ rays_d,
                        const float* __restrict__ aabb,
                        const float* __restrict__ wc,     // [N, 64]
                        const float* __restrict__ sigmas, // [N, 128]
                        const float* __restrict__ rgbs,   // [N, 128, 3]
                        float* __restrict__ out,          // [N, 388]
                        int N)
{
    __shared__ __align__(16) float s_zed[WPB][TF + 8];   // 129 fine edges (+pad)

    const int warp = threadIdx.x >> 5;
    const int lane = threadIdx.x & 31;
    const int ray  = blockIdx.x * WPB + warp;
    if (ray >= N) return;

    // ---- ray + aabb ----
    const float ox = rays_o[3 * ray + 0];
    const float oy = rays_o[3 * ray + 1];
    const float oz = rays_o[3 * ray + 2];
    const float dx = rays_d[3 * ray + 0];
    const float dy = rays_d[3 * ray + 1];
    const float dz = rays_d[3 * ray + 2];

    const float ix = frcp(dx + 1e-15f);
    const float iy = frcp(dy + 1e-15f);
    const float iz = frcp(dz + 1e-15f);
    const float t0x = (aabb[0] - ox) * ix, t1x = (aabb[3] - ox) * ix;
    const float t0y = (aabb[1] - oy) * iy, t1y = (aabb[4] - oy) * iy;
    const float t0z = (aabb[2] - oz) * iz, t1z = (aabb[5] - oz) * iz;

    float nearv = fmaxf(fmaxf(fminf(t0x, t1x), fminf(t0y, t1y)), fminf(t0z, t1z));
    float farv  = fminf(fminf(fmaxf(t0x, t1x), fmaxf(t0y, t1y)), fmaxf(t0z, t1z));
    if (farv < nearv) { nearv = 1e9f; farv = 1e9f; }
    nearv = fmaxf(nearv, 0.05f);
    const float db = (farv - nearv) * (1.0f / 64.0f);   // coarse bin width

    // ---- CDF: lane owns weights {2l, 2l+1} -> intervals 2l, 2l+1 local ----
    const float2 wpair = __ldcs(reinterpret_cast<const float2*>(
        wc + (size_t)ray * T0 + 2 * lane));
    const float wa = wpair.x + 0.01f;
    const float pairw = wa + wpair.y + 0.01f;

    float incl = pairw;
    #pragma unroll
    for (int o = 1; o < 32; o <<= 1) {
        float v = __shfl_up_sync(FULL, incl, o);
        if (lane >= o) incl += v;
    }
    float excl = __shfl_up_sync(FULL, incl, 1);
    if (lane == 0) excl = 0.0f;
    const float inv_tot = frcp(__shfl_sync(FULL, incl, 31));

    // clamps to 1.0 dropped: partial/total <= 1 + ~2e-7; z error bounded by
    // the per-edge saturate below (within rel tolerance by ~4 orders).
    const float c_base = excl * inv_tot;            // C[2l]
    const float c_mid  = (excl + wa) * inv_tot;     // C[2l+1]
    const float c_end  = incl * inv_tot;            // C[2l+2]

    float* zed = s_zed[warp];

    // ---- scatter fine edges: interval k covers u in [C[k], C[k+1]) ----
    constexpr float inv129 = 1.0f / 129.0f;
    #pragma unroll
    for (int h = 0; h < 2; ++h) {
        const int k = 2 * lane + h;
        const float c0 = (h == 0) ? c_base : c_mid;
        const float c1 = (h == 0) ? c_mid : c_end;

        const int j0 = __float2int_ru(fmaf(129.0f, c0, -0.5f));
        const int j1 = __float2int_ru(fmaf(129.0f, c1, -0.5f));

        const float inv_den = frcp(fmaxf(c1 - c0, 1e-12f));
        const float b0 = fmaf(db, (float)k, nearv);
        const float step_t = inv_den * inv129;
        float t = fmaf((float)j0 + 0.5f, inv129, -c0) * inv_den;

        for (int j = j0; j < j1; ++j) {
            zed[j] = fmaf(__saturatef(t), db, b0);   // .SAT on FMA pipe
            t += step_t;
        }
    }
    __syncwarp();

    // ---- blocked compositing: lane owns samples 4l..4l+3 ----
    const float4 z4 = *reinterpret_cast<const float4*>(&zed[4 * lane]);
    const float ztop = zed[TF];                         // zed[128], broadcast
    const float znxt = __shfl_down_sync(FULL, z4.x, 1); // next lane's first edge
    const float e4 = (lane == 31) ? ztop : znxt;

    const float4 sg4 = __ldcs(reinterpret_cast<const float4*>(
        sigmas + (size_t)ray * TF + 4 * lane));

    const float p1 = sg4.x * (z4.y - z4.x);
    const float p2 = p1 + sg4.y * (z4.z - z4.y);
    const float p3 = p2 + sg4.z * (z4.w - z4.z);
    const float Tl = p3 + sg4.w * (e4   - z4.w);   // lane-local optical depth

    // single additive warp scan over lane totals
    float iS = Tl;
    #pragma unroll
    for (int o = 1; o < 32; o <<= 1) {
        float v = __shfl_up_sync(FULL, iS, o);
        if (lane >= o) iS += v;
    }
    float S0 = __shfl_up_sync(FULL, iS, 1);
    if (lane == 0) S0 = 0.0f;

    const float E0 = __expf(-S0);
    const float E1 = __expf(-(S0 + p1));
    const float E2 = __expf(-(S0 + p2));
    const float E3 = __expf(-(S0 + p3));
    const float E4 = __expf(-(S0 + Tl));

    const float w0 = E0 - E1;
    const float w1 = E1 - E2;
    const float w2 = E2 - E3;
    const float w3 = E3 - E4;

    const float zm0 = 0.5f * (z4.x + z4.y);
    const float zm1 = 0.5f * (z4.y + z4.z);
    const float zm2 = 0.5f * (z4.z + z4.w);
    const float zm3 = 0.5f * (z4.w + e4);

    float dep = w0 * zm0 + w1 * zm1 + w2 * zm2 + w3 * zm3;

    // ---- rgb: 3x LDG.128 streaming, compile-time channel mapping ----
    const float4* rg4 = reinterpret_cast<const float4*>(
        rgbs + (size_t)ray * TF * 3) + 3 * lane;
    const float4 f0 = __ldcs(rg4 + 0);
    const float4 f1 = __ldcs(rg4 + 1);
    const float4 f2 = __ldcs(rg4 + 2);

    float img0 = w0 * f0.x + w1 * f0.w + w2 * f1.z + w3 * f2.y;
    float img1 = w0 * f0.y + w1 * f1.x + w2 * f1.w + w3 * f2.z;
    float img2 = w0 * f0.z + w1 * f1.y + w2 * f2.x + w3 * f2.w;

    // ---- branchless contraction + packed xyz streaming stores ----
    float c0x, c0y, c0z, c1x, c1y, c1z, c2x, c2y, c2z, c3x, c3y, c3z;
    contract_pt(zm0, ox, oy, oz, dx, dy, dz, c0x, c0y, c0z);
    contract_pt(zm1, ox, oy, oz, dx, dy, dz, c1x, c1y, c1z);
    contract_pt(zm2, ox, oy, oz, dx, dy, dz, c2x, c2y, c2z);
    contract_pt(zm3, ox, oy, oz, dx, dy, dz, c3x, c3y, c3z);

    const size_t base = (size_t)ray * OUTW;
    float4* xo4 = reinterpret_cast<float4*>(out + base + 4) + 3 * lane;
    __stcs(xo4 + 0, make_float4(c0x, c0y, c0z, c1x));
    __stcs(xo4 + 1, make_float4(c1y, c1z, c2x, c2y));
    __stcs(xo4 + 2, make_float4(c2z, c3x, c3y, c3z));

    // ---- transposed warp reduction: 15 SHFL ----
    #pragma unroll
    for (int o = 16; o >= 8; o >>= 1) {
        img0 += __shfl_down_sync(FULL, img0, o);
        img1 += __shfl_down_sync(FULL, img1, o);
        img2 += __shfl_down_sync(FULL, img2, o);
        dep  += __shfl_down_sync(FULL, dep,  o);
    }
    // partials now in lanes 0..7; lane l fetches quantity (l>>3) from lane (l&7)
    const int src = lane & 7;
    const float a0 = __shfl_sync(FULL, img0, src);
    const float a1 = __shfl_sync(FULL, img1, src);
    const float a2 = __shfl_sync(FULL, img2, src);
    const float a3 = __shfl_sync(FULL, dep,  src);
    const int q = lane >> 3;
    float m = (q == 0) ? a0 : (q == 1) ? a1 : (q == 2) ? a2 : a3;
    #pragma unroll
    for (int o = 4; o > 0; o >>= 1)
        m += __shfl_down_sync(FULL, m, o);
    if (src == 0)
        __stcs(out + base + q, m);   // 4 lanes, one 16B segment
}

extern "C" void kernel_launch(void* const* d_in, const int* in_sizes, int n_in,
                              void* d_out, int out_size)
{
    const float* rays_o = (const float*)d_in[0];
    const float* rays_d = (const float*)d_in[1];
    const float* aabb   = (const float*)d_in[2];
    const float* wc     = (const float*)d_in[3];
    const float* sigmas = (const float*)d_in[4];
    const float* rgbs   = (const float*)d_in[5];
    float* out = (float*)d_out;

    const int N = in_sizes[0] / 3;   // rays_o has N*3 elements
    const int blocks = (N + WPB - 1) / WPB;
    nerf_render_kernel<<<blocks, WPB * 32>>>(
        rays_o, rays_d, aabb, wc, sigmas, rgbs, out, N);
}